// round 7
// baseline (speedup 1.0000x reference)
#include <cuda_runtime.h>
#include <math.h>

// Problem constants
#define NB 16384      // batch rows
#define NK 256        // clusters
#define GRID_P 296    // 2 blocks per SM (148 SMs)
#define BLOCK_P 256
#define WARPS_P (BLOCK_P/32)

// Scratch state (device globals: allocation-free per harness rules)
// __align__(16) is load-bearing: these are accessed through double2*.
static __device__ __align__(16) double g_E[(size_t)NB*NK];   // exp(f/eps), fp64, 33.5 MB
static __device__ __align__(16) double g_v1[NB];
static __device__ __align__(16) double g_v2[NB];
static __device__ __align__(16) double g_R1[NK];
static __device__ __align__(16) double g_R2[NK];
static __device__ __align__(16) double g_R3[NK];
static __device__ __align__(16) double g_ub1[NK];  // adjoint \bar{u}_1
static __device__ __align__(16) double g_ub2[NK];
static __device__ __align__(16) double g_ub3[NK];
static __device__ __align__(16) double g_K2[NK];   // softmax(w) as double
static __device__ float  g_w[NK];
static __device__ float  g_buf[NK];  // SGD momentum buffer

__device__ __forceinline__ double warpAllSum(double v) {
#pragma unroll
    for (int m = 16; m; m >>= 1) v += __shfl_xor_sync(0xffffffffu, v, m);
    return v;
}

// Block-level reduction of per-lane 8-column accumulators into a global K-vector.
// Lane l of every warp owns columns {64j+2l, 64j+2l+1 : j=0..3}.
__device__ __forceinline__ void blockAccum(double* __restrict__ gdst,
                                           const double a0[4], const double a1[4],
                                           int lane, int warp,
                                           double (*sacc)[NK]) {
#pragma unroll
    for (int j = 0; j < 4; j++) {
        int c = j*64 + 2*lane;
        sacc[warp][c]   = a0[j];
        sacc[warp][c+1] = a1[j];
    }
    __syncthreads();
    int t = threadIdx.x;
    double s = 0.0;
#pragma unroll
    for (int wv = 0; wv < WARPS_P; wv++) s += sacc[wv][t];
    atomicAdd(&gdst[t], s);
}

// ---------------------------------------------------------------------------
// init: copy w, zero state, K2 = softmax(w) (f32 math, matching jax.nn.softmax)
// ---------------------------------------------------------------------------
__global__ void k_init(const float* __restrict__ win) {
    __shared__ float  sf[NK];
    __shared__ double sd[NK];
    int j = threadIdx.x;
    float wv = win[j];
    g_w[j] = wv; g_buf[j] = 0.f;
    g_R1[j] = 0.0; g_R2[j] = 0.0; g_R3[j] = 0.0;
    g_ub1[j] = 0.0; g_ub2[j] = 0.0; g_ub3[j] = 0.0;
    sf[j] = wv; __syncthreads();
    for (int s = 128; s; s >>= 1) { if (j < s) sf[j] = fmaxf(sf[j], sf[j+s]); __syncthreads(); }
    float m = sf[0]; __syncthreads();
    float ex = expf(wv - m);
    sd[j] = (double)ex; __syncthreads();
    for (int s = 128; s; s >>= 1) { if (j < s) sd[j] += sd[j+s]; __syncthreads(); }
    float sum = (float)sd[0];
    g_K2[j] = (double)(ex / sum);
}

// ---------------------------------------------------------------------------
// precompute: E = exp(f * (1/eps)) in fp64, and R1[k] = sum_b E[b,k]
// ---------------------------------------------------------------------------
__global__ void __launch_bounds__(BLOCK_P, 2) k_pre(const float* __restrict__ fin) {
    __shared__ double sacc[WARPS_P][NK];
    const double INV_EPS = 1.0 / 0.05;
    int lane = threadIdx.x & 31, warp = threadIdx.x >> 5;
    int gw = blockIdx.x * WARPS_P + warp;
    const int nw = GRID_P * WARPS_P;
    double a0[4], a1[4];
#pragma unroll
    for (int j = 0; j < 4; j++) { a0[j] = 0.0; a1[j] = 0.0; }
    for (int r = gw; r < NB; r += nw) {
        const float2* frow = (const float2*)(fin + (size_t)r*NK);
        double2* erow = (double2*)(g_E + (size_t)r*NK);
#pragma unroll
        for (int j = 0; j < 4; j++) {
            float2 p = frow[j*32 + lane];
            double2 e;
            e.x = exp((double)p.x * INV_EPS);
            e.y = exp((double)p.y * INV_EPS);
            erow[j*32 + lane] = e;
            a0[j] += e.x; a1[j] += e.y;
        }
    }
    blockAccum(g_R1, a0, a1, lane, warp, sacc);
}

// ---------------------------------------------------------------------------
// forward pass (inner iter i): u = K2/Rin on the fly, C[b]=sum u*E,
// v=1/(B*C) stored, Rout[k] += E[b,k]*v[b]
// phase 1: Rin=R1, v->v1, Rout=R2.  phase 2: Rin=R2, v->v2, Rout=R3.
// ---------------------------------------------------------------------------
__global__ void __launch_bounds__(BLOCK_P, 2) fwdPass(int phase) {
    __shared__ double sacc[WARPS_P][NK];
    const double* __restrict__ Rin  = (phase == 1) ? g_R1 : g_R2;
    double* __restrict__ vout       = (phase == 1) ? g_v1 : g_v2;
    double* __restrict__ Rout       = (phase == 1) ? g_R2 : g_R3;
    int lane = threadIdx.x & 31, warp = threadIdx.x >> 5;
    int gw = blockIdx.x * WARPS_P + warp;
    const int nw = GRID_P * WARPS_P;
    double u0[4], u1[4], a0[4], a1[4];
#pragma unroll
    for (int j = 0; j < 4; j++) {
        int c = j*64 + 2*lane;
        u0[j] = g_K2[c]   / Rin[c];
        u1[j] = g_K2[c+1] / Rin[c+1];
        a0[j] = 0.0; a1[j] = 0.0;
    }
    for (int r = gw; r < NB; r += nw) {
        const double2* row = (const double2*)(g_E + (size_t)r*NK);
        double2 e[4];
#pragma unroll
        for (int j = 0; j < 4; j++) e[j] = row[j*32 + lane];
        double c = 0.0;
#pragma unroll
        for (int j = 0; j < 4; j++) c += u0[j]*e[j].x + u1[j]*e[j].y;
        c = warpAllSum(c);
        double v = 1.0 / (16384.0 * c);
        if (lane == 0) vout[r] = v;
#pragma unroll
        for (int j = 0; j < 4; j++) { a0[j] += e[j].x * v; a1[j] += e[j].y * v; }
    }
    blockAccum(Rout, a0, a1, lane, warp, sacc);
}

// ---------------------------------------------------------------------------
// passC: 3rd forward iter fused with backward layer-3:
//   u3=K2/R3; C3[b]; v3=1/(B*C3); S[b]=sum_k u3*E*P  (P = (double)f)
//   vbar3=-S; cbar3 = B*v3^2*S; ub3[k] += E*(cbar3 - v3*P)
// ---------------------------------------------------------------------------
__global__ void __launch_bounds__(BLOCK_P, 2) passC(const float* __restrict__ fin) {
    __shared__ double sacc[WARPS_P][NK];
    int lane = threadIdx.x & 31, warp = threadIdx.x >> 5;
    int gw = blockIdx.x * WARPS_P + warp;
    const int nw = GRID_P * WARPS_P;
    double u0[4], u1[4], a0[4], a1[4];
#pragma unroll
    for (int j = 0; j < 4; j++) {
        int c = j*64 + 2*lane;
        u0[j] = g_K2[c]   / g_R3[c];
        u1[j] = g_K2[c+1] / g_R3[c+1];
        a0[j] = 0.0; a1[j] = 0.0;
    }
    for (int r = gw; r < NB; r += nw) {
        const double2* row = (const double2*)(g_E + (size_t)r*NK);
        const float2* frow = (const float2*)(fin + (size_t)r*NK);
        double2 e[4]; float2 pf[4];
#pragma unroll
        for (int j = 0; j < 4; j++) { e[j] = row[j*32 + lane]; pf[j] = frow[j*32 + lane]; }
        double c = 0.0, s = 0.0;
#pragma unroll
        for (int j = 0; j < 4; j++) {
            double t0 = u0[j]*e[j].x, t1 = u1[j]*e[j].y;
            c += t0 + t1;
            s += t0*(double)pf[j].x + t1*(double)pf[j].y;
        }
        c = warpAllSum(c);
        s = warpAllSum(s);
        double v3 = 1.0 / (16384.0 * c);
        double cbar = 16384.0 * v3 * v3 * s;   // = -B*v3^2 * vbar3, vbar3=-s
#pragma unroll
        for (int j = 0; j < 4; j++) {
            a0[j] += e[j].x * (cbar - v3*(double)pf[j].x);
            a1[j] += e[j].y * (cbar - v3*(double)pf[j].y);
        }
    }
    blockAccum(g_ub3, a0, a1, lane, warp, sacc);
}

// ---------------------------------------------------------------------------
// passC_out (final iteration): Q = B * u3[k] * E * v3[b], written as FLOAT32
// (harness output dtype; fp64 is computed internally, downcast on store).
// ---------------------------------------------------------------------------
__global__ void __launch_bounds__(BLOCK_P, 2) passC_out(float* __restrict__ out) {
    int lane = threadIdx.x & 31, warp = threadIdx.x >> 5;
    int gw = blockIdx.x * WARPS_P + warp;
    const int nw = GRID_P * WARPS_P;
    double u0[4], u1[4];
#pragma unroll
    for (int j = 0; j < 4; j++) {
        int c = j*64 + 2*lane;
        u0[j] = g_K2[c]   / g_R3[c];
        u1[j] = g_K2[c+1] / g_R3[c+1];
    }
    for (int r = gw; r < NB; r += nw) {
        const double2* row = (const double2*)(g_E + (size_t)r*NK);
        float2* orow = (float2*)(out + (size_t)r*NK);
        double2 e[4];
#pragma unroll
        for (int j = 0; j < 4; j++) e[j] = row[j*32 + lane];
        double c = 0.0;
#pragma unroll
        for (int j = 0; j < 4; j++) c += u0[j]*e[j].x + u1[j]*e[j].y;
        c = warpAllSum(c);
        double v3 = 1.0 / (16384.0 * c);
        double scale = 16384.0 * v3;   // B * v3
#pragma unroll
        for (int j = 0; j < 4; j++) {
            float2 o;
            o.x = (float)(u0[j]*e[j].x*scale);
            o.y = (float)(u1[j]*e[j].y*scale);
            orow[j*32 + lane] = o;
        }
    }
}

// ---------------------------------------------------------------------------
// backward pass (layers 2 and 1):
//   rb[k] = -ub_{i+1}[k]*K2[k]/R_{i+1}[k]^2   (== Rbar_{i+1})
//   vbar_i[b] = sum_k E*rb;  cbar_i = -B*v_i^2*vbar_i;  ub_i[k] += E*cbar_i
// layer==2: uses ub3,R3,v2 -> ub2.  layer==1: uses ub2,R2,v1 -> ub1.
// ---------------------------------------------------------------------------
__global__ void __launch_bounds__(BLOCK_P, 2) bwdPass(int layer) {
    __shared__ double sacc[WARPS_P][NK];
    const double* __restrict__ Rv = (layer == 2) ? g_R3  : g_R2;
    const double* __restrict__ ub = (layer == 2) ? g_ub3 : g_ub2;
    const double* __restrict__ vv = (layer == 2) ? g_v2  : g_v1;
    double* __restrict__ uout     = (layer == 2) ? g_ub2 : g_ub1;
    int lane = threadIdx.x & 31, warp = threadIdx.x >> 5;
    int gw = blockIdx.x * WARPS_P + warp;
    const int nw = GRID_P * WARPS_P;
    double rb0[4], rb1[4], a0[4], a1[4];
#pragma unroll
    for (int j = 0; j < 4; j++) {
        int c = j*64 + 2*lane;
        rb0[j] = -ub[c]   * g_K2[c]   / (Rv[c]   * Rv[c]);
        rb1[j] = -ub[c+1] * g_K2[c+1] / (Rv[c+1] * Rv[c+1]);
        a0[j] = 0.0; a1[j] = 0.0;
    }
    for (int r = gw; r < NB; r += nw) {
        const double2* row = (const double2*)(g_E + (size_t)r*NK);
        double2 e[4];
#pragma unroll
        for (int j = 0; j < 4; j++) e[j] = row[j*32 + lane];
        double t = 0.0;
#pragma unroll
        for (int j = 0; j < 4; j++) t += rb0[j]*e[j].x + rb1[j]*e[j].y;
        t = warpAllSum(t);                 // vbar_i[r]
        double vr = vv[r];
        double cb = -16384.0 * vr * vr * t; // cbar_i[r]
#pragma unroll
        for (int j = 0; j < 4; j++) { a0[j] += e[j].x * cb; a1[j] += e[j].y * cb; }
    }
    blockAccum(uout, a0, a1, lane, warp, sacc);
}

// ---------------------------------------------------------------------------
// update: K2bar -> softmax VJP + KL-reg grad, clip-by-norm (f32), momentum
// SGD step (f32), recompute K2=softmax(w), zero accumulators for next iter.
// ---------------------------------------------------------------------------
__global__ void k_update() {
    __shared__ double sd[NK];
    __shared__ float  sf[NK];
    int j = threadIdx.x;
    double K2j = g_K2[j];
    double kbar = g_ub1[j]/g_R1[j] + g_ub2[j]/g_R2[j] + g_ub3[j]/g_R3[j];
    sd[j] = kbar * K2j; __syncthreads();
    for (int s = 128; s; s >>= 1) { if (j < s) sd[j] += sd[j+s]; __syncthreads(); }
    double dot = sd[0]; __syncthreads();
    // softmax VJP + GAMMA * d(reg)/dw,  reg grad = K2/K - 1/K^2
    double g = K2j*(kbar - dot) + 5.0*(K2j*(1.0/256.0) - (1.0/65536.0));
    float gf = (float)g;
    sd[j] = (double)gf * (double)gf; __syncthreads();
    for (int s = 128; s; s >>= 1) { if (j < s) sd[j] += sd[j+s]; __syncthreads(); }
    float norm = (float)sqrt(sd[0]); __syncthreads();
    float sc = fminf(1.0f, 1.0f/(norm + 1e-6f));
    gf *= sc;
    float bf = 0.99f*g_buf[j] + gf; g_buf[j] = bf;   // momentum (buf0=0 -> buf=g)
    float wv = g_w[j] - 0.1f*bf;    g_w[j]   = wv;
    // K2 = softmax(w) (f32 math, cast to double)
    sf[j] = wv; __syncthreads();
    for (int s = 128; s; s >>= 1) { if (j < s) sf[j] = fmaxf(sf[j], sf[j+s]); __syncthreads(); }
    float m = sf[0]; __syncthreads();
    float ex = expf(wv - m);
    sd[j] = (double)ex; __syncthreads();
    for (int s = 128; s; s >>= 1) { if (j < s) sd[j] += sd[j+s]; __syncthreads(); }
    float sum = (float)sd[0];
    g_K2[j] = (double)(ex / sum);
    // zero accumulators for the next outer iteration
    g_R2[j] = 0.0; g_R3[j] = 0.0;
    g_ub1[j] = 0.0; g_ub2[j] = 0.0; g_ub3[j] = 0.0;
}

// ---------------------------------------------------------------------------
extern "C" void kernel_launch(void* const* d_in, const int* in_sizes, int n_in,
                              void* d_out, int out_size) {
    // Select inputs by element count (robust to metadata ordering):
    //   features: 16384*256 = 4194304 f32, w: 256 f32, head: 1 (ignored)
    const float* fin = nullptr;
    const float* win = nullptr;
    for (int i = 0; i < n_in; i++) {
        if (in_sizes[i] == NB*NK)      fin = (const float*)d_in[i];
        else if (in_sizes[i] == NK)    win = (const float*)d_in[i];
    }
    if (!fin) fin = (const float*)d_in[0];
    if (!win) win = (const float*)d_in[1];
    float* out = (float*)d_out;                 // Q [16384, 256], f32 output

    k_init<<<1, NK>>>(win);
    k_pre<<<GRID_P, BLOCK_P>>>(fin);

    // 9 full steps (forward + backward + SGD update)
    for (int it = 0; it < 9; ++it) {
        fwdPass<<<GRID_P, BLOCK_P>>>(1);
        fwdPass<<<GRID_P, BLOCK_P>>>(2);
        passC<<<GRID_P, BLOCK_P>>>(fin);
        bwdPass<<<GRID_P, BLOCK_P>>>(2);
        bwdPass<<<GRID_P, BLOCK_P>>>(1);
        k_update<<<1, NK>>>();
    }
    // 10th step: only the forward matters (Q returned uses pre-update w)
    fwdPass<<<GRID_P, BLOCK_P>>>(1);
    fwdPass<<<GRID_P, BLOCK_P>>>(2);
    passC_out<<<GRID_P, BLOCK_P>>>(out);
}

// round 8
// speedup vs baseline: 3.6251x; 3.6251x over previous
#include <cuda_runtime.h>
#include <math.h>

// ---------------------------------------------------------------------------
// Balanced Sinkhorn, persistent single-kernel version.
//
// Key identity: the reference Sinkhorn row-normalizes (over batch) FIRST each
// iteration, so E -> E * exp(-M_k) (any per-cluster-column shift) leaves Q and
// d(loss)/dw exactly invariant. We shift by the column max so
// E' = exp((f - colmax_k)/eps) in [0,1] fits fp32 and the whole 16.7MB matrix
// is resident in shared memory (113KB/SM) for the entire 10-step solve.
// Row scalars (v, v^2, cbar) stay fp64 (v can reach ~1e12+).
// ---------------------------------------------------------------------------

#define NB 16384
#define NK 256
#define GRID_P 148
#define BLOCK_P 256
#define WARPS_P 8
#define N_OUTER 10

// dynamic shared memory layout (bytes)
#define OFF_RED 0                       // double[256]          2048
#define OFF_V1  2048                    // double[112]           896
#define OFF_V2  2944                    // double[112]           896
#define OFF_E   3840                    // float[111*256]     113664
#define OFF_ACC 117504                  // float[8*256]         8192
#define OFF_U   125696                  // float[256]           1024
#define SMEM_TOTAL 126720

// Global state (device globals: allocation-free). Monotonic across launches
// where required; per-launch state re-zeroed inside the kernel (phase A).
static __device__ unsigned g_tickets;        // monotonic grid-barrier counter
static __device__ unsigned g_cmaxE[NK];      // encoded column max (idempotent)
static __device__ double g_R1[NK], g_R2[NK], g_R3[NK];
static __device__ double g_ub1[NK], g_ub2[NK], g_ub3[NK];
static __device__ double g_K2[NK];
static __device__ float  g_w[NK], g_buf[NK];

// order-preserving float <-> uint encoding for atomicMax
__device__ __forceinline__ unsigned encf(float x) {
    unsigned u = __float_as_uint(x);
    return (u & 0x80000000u) ? ~u : (u | 0x80000000u);
}
__device__ __forceinline__ float decf(unsigned e) {
    unsigned u = (e & 0x80000000u) ? (e & 0x7fffffffu) : ~e;
    return __uint_as_float(u);
}

__device__ __forceinline__ float warpSumF(float v) {
#pragma unroll
    for (int m = 16; m; m >>= 1) v += __shfl_xor_sync(0xffffffffu, v, m);
    return v;
}

// Grid barrier: monotonic ticket counter. All 148 blocks are co-resident
// (1 block/SM by smem). Works across graph replays without reset: barriers
// are globally sequential, ticket t releases at count (t/GRID+1)*GRID.
__device__ __forceinline__ void gridBar() {
    __syncthreads();
    if (threadIdx.x == 0) {
        __threadfence();                                 // release prior writes
        unsigned t = atomicAdd(&g_tickets, 1u);
        unsigned target = (t / GRID_P + 1u) * GRID_P;
        unsigned v;
        do {
            asm volatile("ld.acquire.gpu.u32 %0, [%1];"
                         : "=r"(v) : "l"(&g_tickets) : "memory");
        } while (v < target);
    }
    __syncthreads();
}

// per-warp fp32 partials -> block fp32 -> global fp64 atomic
__device__ __forceinline__ void blockAcc(float* sacc, const float a[8],
                                         int lane, int warp, double* gdst) {
#pragma unroll
    for (int i = 0; i < 4; i++) {
        sacc[warp*NK + 4*lane + i]       = a[i];
        sacc[warp*NK + 128 + 4*lane + i] = a[4+i];
    }
    __syncthreads();
    int t = threadIdx.x;
    float s = 0.f;
#pragma unroll
    for (int w = 0; w < WARPS_P; w++) s += sacc[w*NK + t];
    atomicAdd(&gdst[t], (double)s);
}

// forward pass: c[b]=sum u*E, v=1/(B c) (fp64, saved), Rout[k]+=E*v
__device__ __forceinline__ void fwdBody(const float* sE, const float* su,
                                        double* sv, int nrows, double* Rout,
                                        float* sacc, int lane, int warp) {
    float4 u0 = ((const float4*)su)[lane];
    float4 u1 = ((const float4*)su)[32 + lane];
    float a[8];
#pragma unroll
    for (int i = 0; i < 8; i++) a[i] = 0.f;
#pragma unroll 2
    for (int lr = warp; lr < nrows; lr += WARPS_P) {
        const float4* row = (const float4*)(sE + lr*NK);
        float4 e0 = row[lane], e1 = row[32 + lane];
        float c = e0.x*u0.x + e0.y*u0.y + e0.z*u0.z + e0.w*u0.w
                + e1.x*u1.x + e1.y*u1.y + e1.z*u1.z + e1.w*u1.w;
        c = warpSumF(c);
        c = fmaxf(c, 1e-37f);
        double v = 1.0 / (16384.0 * (double)c);
        if (lane == 0) sv[lr] = v;
        float vf = (float)v;
        a[0] += e0.x*vf; a[1] += e0.y*vf; a[2] += e0.z*vf; a[3] += e0.w*vf;
        a[4] += e1.x*vf; a[5] += e1.y*vf; a[6] += e1.z*vf; a[7] += e1.w*vf;
    }
    blockAcc(sacc, a, lane, warp, Rout);
}

// passC: 3rd forward iter fused with backward layer 3:
//  c, S = sum u*E*P; v3 = 1/(B c); cbar = B v3^2 S; ub3 += E*(cbar - v3*P)
__device__ __forceinline__ void passCBody(const float* sE, const float* su,
                                          const float* __restrict__ fin, int rs,
                                          int nrows, float* sacc, int lane, int warp) {
    float4 u0 = ((const float4*)su)[lane];
    float4 u1 = ((const float4*)su)[32 + lane];
    float a[8];
#pragma unroll
    for (int i = 0; i < 8; i++) a[i] = 0.f;
#pragma unroll 2
    for (int lr = warp; lr < nrows; lr += WARPS_P) {
        const float4* row  = (const float4*)(sE + lr*NK);
        const float4* frow = (const float4*)(fin + (size_t)(rs + lr)*NK);
        float4 e0 = row[lane], e1 = row[32 + lane];
        float4 p0 = frow[lane], p1 = frow[32 + lane];
        float t00 = e0.x*u0.x, t01 = e0.y*u0.y, t02 = e0.z*u0.z, t03 = e0.w*u0.w;
        float t10 = e1.x*u1.x, t11 = e1.y*u1.y, t12 = e1.z*u1.z, t13 = e1.w*u1.w;
        float c = t00+t01+t02+t03 + t10+t11+t12+t13;
        float s = t00*p0.x + t01*p0.y + t02*p0.z + t03*p0.w
                + t10*p1.x + t11*p1.y + t12*p1.z + t13*p1.w;
        c = warpSumF(c);
        s = warpSumF(s);
        c = fmaxf(c, 1e-37f);
        double v3 = 1.0 / (16384.0 * (double)c);
        double cbar = 16384.0 * v3 * v3 * (double)s;
        float cbf = (float)cbar, v3f = (float)v3;
        a[0] += e0.x*(cbf - v3f*p0.x); a[1] += e0.y*(cbf - v3f*p0.y);
        a[2] += e0.z*(cbf - v3f*p0.z); a[3] += e0.w*(cbf - v3f*p0.w);
        a[4] += e1.x*(cbf - v3f*p1.x); a[5] += e1.y*(cbf - v3f*p1.y);
        a[6] += e1.z*(cbf - v3f*p1.z); a[7] += e1.w*(cbf - v3f*p1.w);
    }
    blockAcc(sacc, a, lane, warp, g_ub3);
}

// backward layer: t[b]=sum rb*E; cb=-B v^2 t; ub_out += E*cb
__device__ __forceinline__ void bwdBody(const float* sE, const float* su,
                                        const double* sv, int nrows, double* gdst,
                                        float* sacc, int lane, int warp) {
    float4 b0 = ((const float4*)su)[lane];
    float4 b1 = ((const float4*)su)[32 + lane];
    float a[8];
#pragma unroll
    for (int i = 0; i < 8; i++) a[i] = 0.f;
#pragma unroll 2
    for (int lr = warp; lr < nrows; lr += WARPS_P) {
        const float4* row = (const float4*)(sE + lr*NK);
        float4 e0 = row[lane], e1 = row[32 + lane];
        float t = e0.x*b0.x + e0.y*b0.y + e0.z*b0.z + e0.w*b0.w
                + e1.x*b1.x + e1.y*b1.y + e1.z*b1.z + e1.w*b1.w;
        t = warpSumF(t);
        double vr = sv[lr];
        double cb = -16384.0 * vr * vr * (double)t;
        cb = fmin(fmax(cb, -1e38), 1e38);       // pathological-row insurance
        float cbf = (float)cb;
        a[0] += e0.x*cbf; a[1] += e0.y*cbf; a[2] += e0.z*cbf; a[3] += e0.w*cbf;
        a[4] += e1.x*cbf; a[5] += e1.y*cbf; a[6] += e1.z*cbf; a[7] += e1.w*cbf;
    }
    blockAcc(sacc, a, lane, warp, gdst);
}

// output pass: Q = (E * (B*v3)) * u3, written fp32
__device__ __forceinline__ void outBody(const float* sE, const float* su,
                                        float* __restrict__ out, int rs,
                                        int nrows, int lane, int warp) {
    float4 u0 = ((const float4*)su)[lane];
    float4 u1 = ((const float4*)su)[32 + lane];
#pragma unroll 2
    for (int lr = warp; lr < nrows; lr += WARPS_P) {
        const float4* row = (const float4*)(sE + lr*NK);
        float4 e0 = row[lane], e1 = row[32 + lane];
        float c = e0.x*u0.x + e0.y*u0.y + e0.z*u0.z + e0.w*u0.w
                + e1.x*u1.x + e1.y*u1.y + e1.z*u1.z + e1.w*u1.w;
        c = warpSumF(c);
        c = fmaxf(c, 1e-37f);
        double v3 = 1.0 / (16384.0 * (double)c);
        float bs = (float)(16384.0 * v3);       // B * v3
        float4 o0, o1;
        o0.x = (e0.x*bs)*u0.x; o0.y = (e0.y*bs)*u0.y;
        o0.z = (e0.z*bs)*u0.z; o0.w = (e0.w*bs)*u0.w;
        o1.x = (e1.x*bs)*u1.x; o1.y = (e1.y*bs)*u1.y;
        o1.z = (e1.z*bs)*u1.z; o1.w = (e1.w*bs)*u1.w;
        float4* orow = (float4*)(out + (size_t)(rs + lr)*NK);
        orow[lane] = o0;
        orow[32 + lane] = o1;
    }
}

__global__ void __launch_bounds__(BLOCK_P, 1)
sinkhorn_persist(const float* __restrict__ fin, const float* __restrict__ win,
                 float* __restrict__ out) {
    extern __shared__ char smem[];
    double* sred = (double*)(smem + OFF_RED);
    double* sv1  = (double*)(smem + OFF_V1);
    double* sv2  = (double*)(smem + OFF_V2);
    float*  sE   = (float*) (smem + OFF_E);
    float*  sacc = (float*) (smem + OFF_ACC);
    float*  su   = (float*) (smem + OFF_U);

    const int tid  = threadIdx.x;
    const int lane = tid & 31, warp = tid >> 5;
    const int bid  = blockIdx.x;
    const int rs = (NB * bid) / GRID_P;
    const int re = (NB * (bid + 1)) / GRID_P;
    const int nrows = re - rs;

    // ---- phase A: per-launch init (block 0) + column-max partials ----
    if (bid == 0) {
        float wv = win[tid];
        g_w[tid] = wv; g_buf[tid] = 0.f;
        __stcg(&g_R1[tid], 0.0); __stcg(&g_R2[tid], 0.0); __stcg(&g_R3[tid], 0.0);
        __stcg(&g_ub1[tid], 0.0); __stcg(&g_ub2[tid], 0.0); __stcg(&g_ub3[tid], 0.0);
        // K2 = softmax(w), f32 math (matches jax.nn.softmax on f32)
        su[tid] = wv; __syncthreads();
        for (int s = 128; s; s >>= 1) { if (tid < s) su[tid] = fmaxf(su[tid], su[tid+s]); __syncthreads(); }
        float m = su[0]; __syncthreads();
        float ex = expf(wv - m);
        sred[tid] = (double)ex; __syncthreads();
        for (int s = 128; s; s >>= 1) { if (tid < s) sred[tid] += sred[tid+s]; __syncthreads(); }
        float sum = (float)sred[0];
        __stcg(&g_K2[tid], (double)(ex / sum));
    }
    {   // column max over this block's rows (thread t owns column t)
        float m = -3.4e38f;
        for (int r = rs; r < re; r++) m = fmaxf(m, fin[(size_t)r*NK + tid]);
        atomicMax(&g_cmaxE[tid], encf(m));  // idempotent across replays (0 < any enc)
    }
    gridBar();

    // ---- phase B: build E' = exp((f - colmax)/eps) into smem, R1 = colsum ----
    {
        float Mt = decf(__ldcg(&g_cmaxE[tid]));
        double r1 = 0.0;
        for (int r = rs; r < re; r++) {
            float e = expf((fin[(size_t)r*NK + tid] - Mt) * 20.0f);
            sE[(r - rs)*NK + tid] = e;
            r1 += (double)e;
        }
        atomicAdd(&g_R1[tid], r1);
    }
    gridBar();

    // ---- outer optimization loop ----
    for (int it = 0; it < N_OUTER; ++it) {
        const bool last = (it == N_OUTER - 1);

        // fwd1: u1 = K2/R1 -> sv1, R2
        su[tid] = (float)(__ldcg(&g_K2[tid]) / __ldcg(&g_R1[tid]));
        __syncthreads();
        fwdBody(sE, su, sv1, nrows, g_R2, sacc, lane, warp);
        gridBar();

        // fwd2: u2 = K2/R2 -> sv2, R3
        su[tid] = (float)(__ldcg(&g_K2[tid]) / __ldcg(&g_R2[tid]));
        __syncthreads();
        fwdBody(sE, su, sv2, nrows, g_R3, sacc, lane, warp);
        gridBar();

        if (!last) {
            // passC: u3 = K2/R3 -> ub3
            su[tid] = (float)(__ldcg(&g_K2[tid]) / __ldcg(&g_R3[tid]));
            __syncthreads();
            passCBody(sE, su, fin, rs, nrows, sacc, lane, warp);
            gridBar();

            // bwd layer 2: rb = -ub3*K2/R3^2, uses v2 -> ub2
            { double R = __ldcg(&g_R3[tid]);
              su[tid] = (float)(-__ldcg(&g_ub3[tid]) * __ldcg(&g_K2[tid]) / (R*R)); }
            __syncthreads();
            bwdBody(sE, su, sv2, nrows, g_ub2, sacc, lane, warp);
            gridBar();

            // bwd layer 1: rb = -ub2*K2/R2^2, uses v1 -> ub1
            { double R = __ldcg(&g_R2[tid]);
              su[tid] = (float)(-__ldcg(&g_ub2[tid]) * __ldcg(&g_K2[tid]) / (R*R)); }
            __syncthreads();
            bwdBody(sE, su, sv1, nrows, g_ub1, sacc, lane, warp);
            gridBar();

            // SGD update (block 0 only): identical math to verified R7 kernel
            if (bid == 0) {
                double K2j = __ldcg(&g_K2[tid]);
                double kb = __ldcg(&g_ub1[tid]) / __ldcg(&g_R1[tid])
                          + __ldcg(&g_ub2[tid]) / __ldcg(&g_R2[tid])
                          + __ldcg(&g_ub3[tid]) / __ldcg(&g_R3[tid]);
                sred[tid] = kb * K2j; __syncthreads();
                for (int s = 128; s; s >>= 1) { if (tid < s) sred[tid] += sred[tid+s]; __syncthreads(); }
                double dot = sred[0]; __syncthreads();
                double g = K2j*(kb - dot) + 5.0*(K2j*(1.0/256.0) - (1.0/65536.0));
                float gf = (float)g;
                sred[tid] = (double)gf * (double)gf; __syncthreads();
                for (int s = 128; s; s >>= 1) { if (tid < s) sred[tid] += sred[tid+s]; __syncthreads(); }
                float norm = (float)sqrt(sred[0]); __syncthreads();
                gf *= fminf(1.0f, 1.0f/(norm + 1e-6f));
                float bf = 0.99f*g_buf[tid] + gf; g_buf[tid] = bf;
                float wv = g_w[tid] - 0.1f*bf;    g_w[tid]  = wv;
                su[tid] = wv; __syncthreads();
                for (int s = 128; s; s >>= 1) { if (tid < s) su[tid] = fmaxf(su[tid], su[tid+s]); __syncthreads(); }
                float m = su[0]; __syncthreads();
                float ex = expf(wv - m);
                sred[tid] = (double)ex; __syncthreads();
                for (int s = 128; s; s >>= 1) { if (tid < s) sred[tid] += sred[tid+s]; __syncthreads(); }
                float sum = (float)sred[0];
                __stcg(&g_K2[tid], (double)(ex / sum));
                __stcg(&g_R2[tid], 0.0);  __stcg(&g_R3[tid], 0.0);
                __stcg(&g_ub1[tid], 0.0); __stcg(&g_ub2[tid], 0.0); __stcg(&g_ub3[tid], 0.0);
            }
            gridBar();
        } else {
            // final: Q uses pre-update w; write output and exit
            su[tid] = (float)(__ldcg(&g_K2[tid]) / __ldcg(&g_R3[tid]));
            __syncthreads();
            outBody(sE, su, out, rs, nrows, lane, warp);
        }
    }
}

// ---------------------------------------------------------------------------
extern "C" void kernel_launch(void* const* d_in, const int* in_sizes, int n_in,
                              void* d_out, int out_size) {
    // Select inputs by element count (robust to metadata ordering):
    //   features: 4194304 f32, w: 256 f32, head: scalar (ignored)
    const float* fin = nullptr;
    const float* win = nullptr;
    for (int i = 0; i < n_in; i++) {
        if (in_sizes[i] == NB*NK)   fin = (const float*)d_in[i];
        else if (in_sizes[i] == NK) win = (const float*)d_in[i];
    }
    if (!fin) fin = (const float*)d_in[0];
    if (!win) win = (const float*)d_in[1];
    float* out = (float*)d_out;

    cudaFuncSetAttribute(sinkhorn_persist,
                         cudaFuncAttributeMaxDynamicSharedMemorySize, SMEM_TOTAL);
    sinkhorn_persist<<<GRID_P, BLOCK_P, SMEM_TOTAL>>>(fin, win, out);
}

// round 9
// speedup vs baseline: 7.5579x; 2.0849x over previous
#include <cuda_runtime.h>
#include <math.h>

// ---------------------------------------------------------------------------
// Balanced Sinkhorn, persistent single-kernel, zero per-row FP64.
// E' = exp((f - colmax)/eps) in [0,1] (column shift is exactly invariant since
// the reference row-normalizes first) lives entirely in shared memory.
// Per-row scalars factored as r = 1/c so every product stays in fp32 range:
//   v = r/B,  cb = -(t*r)*(r/B),  cbar = (s*r)*(r/B),  Q-scale = r.
// ---------------------------------------------------------------------------

#define NB 16384
#define NK 256
#define GRID_P 148
#define BLOCK_P 512
#define WARPS_P 16
#define N_OUTER 10
#define INV_B 6.103515625e-05f   // 1/16384 (exact)

// shared memory layout (bytes)
#define OFF_RED  0        // double[256]  2048
#define OFF_K2   2048     // double[256]  2048
#define OFF_R1   4096     // double[256]  2048
#define OFF_W    6144     // float[256]   1024
#define OFF_BUF  7168     // float[256]   1024
#define OFF_V1   8192     // float[112]    448
#define OFF_V2   8640     // float[112]    448
#define OFF_U    9088     // float[256]   1024
#define OFF_ACC  10112    // float[16*256] 16384
#define OFF_E    26496    // float[111*256] 113664
#define SMEM_TOTAL 140160

// Global state (allocation-free). tickets monotonic across graph replays;
// accumulators re-zeroed inside the kernel each launch; cmax idempotent.
static __device__ unsigned g_tickets;
static __device__ unsigned g_cmax[NK];
static __device__ double g_R1[NK];
static __device__ double g_R2[2][NK], g_R3[2][NK];
static __device__ double g_ub1[2][NK], g_ub2[2][NK], g_ub3[2][NK];

__device__ __forceinline__ float frcp(float x) {
    float r; asm("rcp.approx.f32 %0, %1;" : "=f"(r) : "f"(x)); return r;
}
// fp32-seeded double reciprocal with one DP Newton step (~2^-46)
__device__ __forceinline__ double rcpd(double x) {
    double r = (double)frcp((float)x);
    return r * (2.0 - x * r);
}
__device__ __forceinline__ unsigned encf(float x) {
    unsigned u = __float_as_uint(x);
    return (u & 0x80000000u) ? ~u : (u | 0x80000000u);
}
__device__ __forceinline__ float decf(unsigned e) {
    unsigned u = (e & 0x80000000u) ? (e & 0x7fffffffu) : ~e;
    return __uint_as_float(u);
}
__device__ __forceinline__ float warpSumF(float v) {
#pragma unroll
    for (int m = 16; m; m >>= 1) v += __shfl_xor_sync(0xffffffffu, v, m);
    return v;
}

// Grid barrier: monotonic ticket counter, all 148 blocks co-resident.
__device__ __forceinline__ void gridBar() {
    __syncthreads();
    if (threadIdx.x == 0) {
        __threadfence();
        unsigned t = atomicAdd(&g_tickets, 1u);
        unsigned target = (t / GRID_P + 1u) * GRID_P;
        for (;;) {
            unsigned v;
            asm volatile("ld.acquire.gpu.u32 %0, [%1];"
                         : "=r"(v) : "l"(&g_tickets) : "memory");
            if (v >= target) break;
            __nanosleep(64);
        }
    }
    __syncthreads();
}

// per-warp fp32 partials -> block fp32 -> global fp64 atomic
__device__ __forceinline__ void blockAcc(float* sacc, const float a[8],
                                         int lane, int warp, int tid,
                                         double* gdst) {
    float4* dst = (float4*)(sacc + warp * NK);
    dst[lane]      = make_float4(a[0], a[1], a[2], a[3]);
    dst[32 + lane] = make_float4(a[4], a[5], a[6], a[7]);
    __syncthreads();
    if (tid < NK) {
        float s = 0.f;
#pragma unroll
        for (int w = 0; w < WARPS_P; w++) s += sacc[w * NK + tid];
        atomicAdd(&gdst[tid], (double)s);
    }
}

// fwd: c[b]=sum u*E; r=1/c stored; Rout[k] += E*(r/B)
__device__ __forceinline__ void fwdBody(const float* sE, const float* su,
                                        float* svf, int nrows, double* Rout,
                                        float* sacc, int lane, int warp, int tid) {
    float4 u0 = ((const float4*)su)[lane];
    float4 u1 = ((const float4*)su)[32 + lane];
    float a[8];
#pragma unroll
    for (int i = 0; i < 8; i++) a[i] = 0.f;
#pragma unroll 2
    for (int lr = warp; lr < nrows; lr += WARPS_P) {
        const float4* row = (const float4*)(sE + lr * NK);
        float4 e0 = row[lane], e1 = row[32 + lane];
        float c = e0.x*u0.x + e0.y*u0.y + e0.z*u0.z + e0.w*u0.w
                + e1.x*u1.x + e1.y*u1.y + e1.z*u1.z + e1.w*u1.w;
        c = warpSumF(c);
        c = fmaxf(c, 1e-37f);
        float r = frcp(c);                 // = B*v
        if (lane == 0) svf[lr] = r;
        float vf = r * INV_B;              // = v
        a[0] += e0.x*vf; a[1] += e0.y*vf; a[2] += e0.z*vf; a[3] += e0.w*vf;
        a[4] += e1.x*vf; a[5] += e1.y*vf; a[6] += e1.z*vf; a[7] += e1.w*vf;
    }
    blockAcc(sacc, a, lane, warp, tid, Rout);
}

// passC (3rd fwd fused with bwd layer 3):
//  c, s=sum u*E*P; r=1/c; cbar=(s*r)*(r/B); v3=r/B; ub3 += E*(cbar - v3*P)
__device__ __forceinline__ void passCBody(const float* sE, const float* su,
                                          const float* __restrict__ fin, int rs,
                                          int nrows, double* gdst, float* sacc,
                                          int lane, int warp, int tid) {
    float4 u0 = ((const float4*)su)[lane];
    float4 u1 = ((const float4*)su)[32 + lane];
    float a[8];
#pragma unroll
    for (int i = 0; i < 8; i++) a[i] = 0.f;
#pragma unroll 2
    for (int lr = warp; lr < nrows; lr += WARPS_P) {
        const float4* row  = (const float4*)(sE + lr * NK);
        const float4* frow = (const float4*)(fin + (size_t)(rs + lr) * NK);
        float4 e0 = row[lane], e1 = row[32 + lane];
        float4 p0 = frow[lane], p1 = frow[32 + lane];
        float t00 = e0.x*u0.x, t01 = e0.y*u0.y, t02 = e0.z*u0.z, t03 = e0.w*u0.w;
        float t10 = e1.x*u1.x, t11 = e1.y*u1.y, t12 = e1.z*u1.z, t13 = e1.w*u1.w;
        float c = t00+t01+t02+t03 + t10+t11+t12+t13;
        float s = t00*p0.x + t01*p0.y + t02*p0.z + t03*p0.w
                + t10*p1.x + t11*p1.y + t12*p1.z + t13*p1.w;
        c = warpSumF(c);
        s = warpSumF(s);
        c = fmaxf(c, 1e-37f);
        float r = frcp(c);
        float v3f = r * INV_B;
        float cbf = (s * r) * v3f;        // = B*v3^2*s, overflow-safe ordering
        a[0] += e0.x*(cbf - v3f*p0.x); a[1] += e0.y*(cbf - v3f*p0.y);
        a[2] += e0.z*(cbf - v3f*p0.z); a[3] += e0.w*(cbf - v3f*p0.w);
        a[4] += e1.x*(cbf - v3f*p1.x); a[5] += e1.y*(cbf - v3f*p1.y);
        a[6] += e1.z*(cbf - v3f*p1.z); a[7] += e1.w*(cbf - v3f*p1.w);
    }
    blockAcc(sacc, a, lane, warp, tid, gdst);
}

// bwd layer: t[b]=sum rb*E; cb=-(t*r)*(r/B); ub_out += E*cb
__device__ __forceinline__ void bwdBody(const float* sE, const float* su,
                                        const float* svf, int nrows, double* gdst,
                                        float* sacc, int lane, int warp, int tid) {
    float4 b0 = ((const float4*)su)[lane];
    float4 b1 = ((const float4*)su)[32 + lane];
    float a[8];
#pragma unroll
    for (int i = 0; i < 8; i++) a[i] = 0.f;
#pragma unroll 2
    for (int lr = warp; lr < nrows; lr += WARPS_P) {
        const float4* row = (const float4*)(sE + lr * NK);
        float4 e0 = row[lane], e1 = row[32 + lane];
        float t = e0.x*b0.x + e0.y*b0.y + e0.z*b0.z + e0.w*b0.w
                + e1.x*b1.x + e1.y*b1.y + e1.z*b1.z + e1.w*b1.w;
        t = warpSumF(t);
        float r = svf[lr];
        float cbf = -(t * r) * (r * INV_B);   // = -B*v^2*t, safe ordering
        a[0] += e0.x*cbf; a[1] += e0.y*cbf; a[2] += e0.z*cbf; a[3] += e0.w*cbf;
        a[4] += e1.x*cbf; a[5] += e1.y*cbf; a[6] += e1.z*cbf; a[7] += e1.w*cbf;
    }
    blockAcc(sacc, a, lane, warp, tid, gdst);
}

// output: Q = E * (B*v3) * u3, fp32; r refined with one fp32 Newton
__device__ __forceinline__ void outBody(const float* sE, const float* su,
                                        float* __restrict__ out, int rs,
                                        int nrows, int lane, int warp) {
    float4 u0 = ((const float4*)su)[lane];
    float4 u1 = ((const float4*)su)[32 + lane];
#pragma unroll 2
    for (int lr = warp; lr < nrows; lr += WARPS_P) {
        const float4* row = (const float4*)(sE + lr * NK);
        float4 e0 = row[lane], e1 = row[32 + lane];
        float c = e0.x*u0.x + e0.y*u0.y + e0.z*u0.z + e0.w*u0.w
                + e1.x*u1.x + e1.y*u1.y + e1.z*u1.z + e1.w*u1.w;
        c = warpSumF(c);
        c = fmaxf(c, 1e-37f);
        float r0 = frcp(c);
        float bs = r0 * (2.0f - c * r0);  // refined 1/c = B*v3
        float4 o0, o1;
        o0.x = (e0.x*bs)*u0.x; o0.y = (e0.y*bs)*u0.y;
        o0.z = (e0.z*bs)*u0.z; o0.w = (e0.w*bs)*u0.w;
        o1.x = (e1.x*bs)*u1.x; o1.y = (e1.y*bs)*u1.y;
        o1.z = (e1.z*bs)*u1.z; o1.w = (e1.w*bs)*u1.w;
        float4* orow = (float4*)(out + (size_t)(rs + lr) * NK);
        orow[lane] = o0;
        orow[32 + lane] = o1;
    }
}

__global__ void __launch_bounds__(BLOCK_P, 1)
sinkhorn_persist(const float* __restrict__ fin, const float* __restrict__ win,
                 float* __restrict__ out) {
    extern __shared__ char smem[];
    double* sred = (double*)(smem + OFF_RED);
    double* sK2  = (double*)(smem + OFF_K2);
    double* sR1  = (double*)(smem + OFF_R1);
    float*  sw   = (float*) (smem + OFF_W);
    float*  sbuf = (float*) (smem + OFF_BUF);
    float*  sv1  = (float*) (smem + OFF_V1);
    float*  sv2  = (float*) (smem + OFF_V2);
    float*  su   = (float*) (smem + OFF_U);
    float*  sacc = (float*) (smem + OFF_ACC);
    float*  sE   = (float*) (smem + OFF_E);

    const int tid  = threadIdx.x;
    const int lane = tid & 31, warp = tid >> 5;
    const int bid  = blockIdx.x;
    const int rs = (NB * bid) / GRID_P;
    const int re = (NB * (bid + 1)) / GRID_P;
    const int nrows = re - rs;

    // ---- phase A: zero global accumulators (block 0), local w/buf/K2 (all),
    //      column-max partials (all) ----
    if (bid == 0 && tid < NK) {
        __stcg(&g_R1[tid], 0.0);
#pragma unroll
        for (int s2 = 0; s2 < 2; s2++) {
            __stcg(&g_R2[s2][tid], 0.0);  __stcg(&g_R3[s2][tid], 0.0);
            __stcg(&g_ub1[s2][tid], 0.0); __stcg(&g_ub2[s2][tid], 0.0);
            __stcg(&g_ub3[s2][tid], 0.0);
        }
    }
    if (tid < NK) { float wv = win[tid]; sw[tid] = wv; sbuf[tid] = 0.f; su[tid] = wv; }
    __syncthreads();
    for (int s = 128; s; s >>= 1) { if (tid < s) su[tid] = fmaxf(su[tid], su[tid+s]); __syncthreads(); }
    { float m = su[0]; __syncthreads();
      float ex = 0.f;
      if (tid < NK) { ex = expf(sw[tid] - m); sred[tid] = (double)ex; }
      __syncthreads();
      for (int s = 128; s; s >>= 1) { if (tid < s) sred[tid] += sred[tid+s]; __syncthreads(); }
      float ssum = (float)sred[0]; __syncthreads();
      if (tid < NK) sK2[tid] = (double)(ex / ssum);
    }
    {   // column max: 512 threads = 2 row-halves x 256 columns
        int col = tid & 255, half = tid >> 8;
        float mx = -3.4e38f;
        for (int r = rs + half; r < re; r += 2)
            mx = fmaxf(mx, fin[(size_t)r * NK + col]);
        atomicMax(&g_cmax[col], encf(mx));   // idempotent across replays
    }
    gridBar();

    // ---- phase B: build E' = exp((f-colmax)*20) into smem; R1 = colsum ----
    {
        int col = tid & 255, half = tid >> 8;
        float Mt = decf(__ldcg(&g_cmax[col]));
        float r1p = 0.f;
        for (int r = rs + half; r < re; r += 2) {
            float e = expf((fin[(size_t)r * NK + col] - Mt) * 20.0f);
            sE[(r - rs) * NK + col] = e;
            r1p += e;
        }
        atomicAdd(&g_R1[col], (double)r1p);
    }
    gridBar();
    if (tid < NK) sR1[tid] = __ldcg(&g_R1[tid]);
    __syncthreads();

    // ---- outer loop ----
    for (int it = 0; it < N_OUTER; ++it) {
        const int s = it & 1;
        const bool last = (it == N_OUTER - 1);

        // fwd1: u1 = K2/R1 -> sv1, R2[s]
        if (tid < NK) su[tid] = (float)sK2[tid] / (float)sR1[tid];
        __syncthreads();
        fwdBody(sE, su, sv1, nrows, g_R2[s], sacc, lane, warp, tid);
        gridBar();

        // zero next iteration's accumulator slot (block 0; race-free: slot s^1
        // was last read before this barrier, first written after two more)
        if (bid == 0 && !last && tid < NK) {
            int t2 = s ^ 1;
            __stcg(&g_R2[t2][tid], 0.0);  __stcg(&g_R3[t2][tid], 0.0);
            __stcg(&g_ub1[t2][tid], 0.0); __stcg(&g_ub2[t2][tid], 0.0);
            __stcg(&g_ub3[t2][tid], 0.0);
        }

        // fwd2: u2 = K2/R2 -> sv2, R3[s]
        if (tid < NK) su[tid] = (float)sK2[tid] / (float)__ldcg(&g_R2[s][tid]);
        __syncthreads();
        fwdBody(sE, su, sv2, nrows, g_R3[s], sacc, lane, warp, tid);
        gridBar();

        if (!last) {
            // passC: u3 = K2/R3 -> ub3[s]
            if (tid < NK) su[tid] = (float)sK2[tid] / (float)__ldcg(&g_R3[s][tid]);
            __syncthreads();
            passCBody(sE, su, fin, rs, nrows, g_ub3[s], sacc, lane, warp, tid);
            gridBar();

            // bwd layer 2: rb = -ub3*K2/R3^2 (K-side, cheap DP), uses sv2 -> ub2[s]
            if (tid < NK) {
                double R = __ldcg(&g_R3[s][tid]);
                double rd = (double)frcp((float)R);
                su[tid] = (float)((-__ldcg(&g_ub3[s][tid]) * sK2[tid] * rd) * rd);
            }
            __syncthreads();
            bwdBody(sE, su, sv2, nrows, g_ub2[s], sacc, lane, warp, tid);
            gridBar();

            // bwd layer 1: rb = -ub2*K2/R2^2, uses sv1 -> ub1[s]
            if (tid < NK) {
                double R = __ldcg(&g_R2[s][tid]);
                double rd = (double)frcp((float)R);
                su[tid] = (float)((-__ldcg(&g_ub2[s][tid]) * sK2[tid] * rd) * rd);
            }
            __syncthreads();
            bwdBody(sE, su, sv1, nrows, g_ub1[s], sacc, lane, warp, tid);
            gridBar();

            // SGD update: redundant per block (deterministic, no extra barrier)
            double K2j = 0.0, kb = 0.0;
            if (tid < NK) {
                K2j = sK2[tid];
                kb = __ldcg(&g_ub1[s][tid]) * rcpd(sR1[tid])
                   + __ldcg(&g_ub2[s][tid]) * rcpd(__ldcg(&g_R2[s][tid]))
                   + __ldcg(&g_ub3[s][tid]) * rcpd(__ldcg(&g_R3[s][tid]));
                sred[tid] = kb * K2j;
            }
            __syncthreads();
            for (int st = 128; st; st >>= 1) { if (tid < st) sred[tid] += sred[tid+st]; __syncthreads(); }
            double dot = sred[0]; __syncthreads();
            float gf = 0.f;
            if (tid < NK) {
                double g = K2j*(kb - dot) + 5.0*(K2j*(1.0/256.0) - (1.0/65536.0));
                gf = (float)g;
                sred[tid] = (double)gf * (double)gf;
            }
            __syncthreads();
            for (int st = 128; st; st >>= 1) { if (tid < st) sred[tid] += sred[tid+st]; __syncthreads(); }
            float norm = (float)sqrt(sred[0]); __syncthreads();
            if (tid < NK) {
                gf *= fminf(1.0f, 1.0f/(norm + 1e-6f));
                float bf = 0.99f*sbuf[tid] + gf; sbuf[tid] = bf;
                float wv = sw[tid] - 0.1f*bf;    sw[tid]   = wv;
                su[tid] = wv;
            }
            __syncthreads();
            for (int st = 128; st; st >>= 1) { if (tid < st) su[tid] = fmaxf(su[tid], su[tid+st]); __syncthreads(); }
            float m = su[0]; __syncthreads();
            float ex = 0.f;
            if (tid < NK) { ex = expf(sw[tid] - m); sred[tid] = (double)ex; }
            __syncthreads();
            for (int st = 128; st; st >>= 1) { if (tid < st) sred[tid] += sred[tid+st]; __syncthreads(); }
            float ssum = (float)sred[0]; __syncthreads();
            if (tid < NK) sK2[tid] = (double)(ex / ssum);
            __syncthreads();
        } else {
            // final: Q uses pre-update w
            if (tid < NK) su[tid] = (float)sK2[tid] / (float)__ldcg(&g_R3[s][tid]);
            __syncthreads();
            outBody(sE, su, out, rs, nrows, lane, warp);
        }
    }
}

// ---------------------------------------------------------------------------
extern "C" void kernel_launch(void* const* d_in, const int* in_sizes, int n_in,
                              void* d_out, int out_size) {
    const float* fin = nullptr;
    const float* win = nullptr;
    for (int i = 0; i < n_in; i++) {
        if (in_sizes[i] == NB*NK)   fin = (const float*)d_in[i];
        else if (in_sizes[i] == NK) win = (const float*)d_in[i];
    }
    if (!fin) fin = (const float*)d_in[0];
    if (!win) win = (const float*)d_in[1];
    float* out = (float*)d_out;

    cudaFuncSetAttribute(sinkhorn_persist,
                         cudaFuncAttributeMaxDynamicSharedMemorySize, SMEM_TOTAL);
    sinkhorn_persist<<<GRID_P, BLOCK_P, SMEM_TOTAL>>>(fin, win, out);
}